// round 1
// baseline (speedup 1.0000x reference)
#include <cuda_runtime.h>

#define D     64
#define BM    128
#define BN    128
#define PAD   132           // k-major row stride (floats), keeps 16B alignment
#define GAMMA 0.015625f

// scratch for precomputed -gamma * ||row||^2
__device__ float g_xs[8192];
__device__ float g_ys[8192];

// ---------------------------------------------------------------------------
// packed f32x2 helpers (Blackwell FFMA2 path)
// ---------------------------------------------------------------------------
__device__ __forceinline__ unsigned long long pack2(float x, float y) {
    unsigned long long r;
    asm("mov.b64 %0, {%1, %2};" : "=l"(r) : "f"(x), "f"(y));
    return r;
}
__device__ __forceinline__ unsigned long long fma2(unsigned long long a,
                                                   unsigned long long b,
                                                   unsigned long long c) {
    unsigned long long d;
    asm("fma.rn.f32x2 %0, %1, %2, %3;" : "=l"(d) : "l"(a), "l"(b), "l"(c));
    return d;
}
__device__ __forceinline__ float2 unpack2(unsigned long long v) {
    float2 f;
    asm("mov.b64 {%0, %1}, %2;" : "=f"(f.x), "=f"(f.y) : "l"(v));
    return f;
}

// ---------------------------------------------------------------------------
// norms: one warp per row, writes -gamma * sum(x^2)
// which = 0 -> g_xs, 1 -> g_ys
// ---------------------------------------------------------------------------
__global__ void __launch_bounds__(256)
norm_kernel(const float* __restrict__ X, int rows, int which) {
    int w    = blockIdx.x * 8 + (threadIdx.x >> 5);
    int lane = threadIdx.x & 31;
    if (w >= rows) return;
    const float* r = X + (size_t)w * D;
    float v0 = r[lane];
    float v1 = r[lane + 32];
    float s  = v0 * v0 + v1 * v1;
#pragma unroll
    for (int o = 16; o; o >>= 1) s += __shfl_xor_sync(0xffffffffu, s, o);
    if (lane == 0) {
        float* out = which ? g_ys : g_xs;
        out[w] = -GAMMA * s;
    }
}

// ---------------------------------------------------------------------------
// main: 128x128 block tile, 8x8 per thread, K=64 single shot, f32x2 FMAs
// ---------------------------------------------------------------------------
extern __shared__ float smem_dyn[];

__global__ void __launch_bounds__(256)
rbf_kernel(const float* __restrict__ A, const float* __restrict__ B,
           float* __restrict__ out, int M, int N) {
    float* As = smem_dyn;            // [D][PAD]  k-major: As[k*PAD + row]
    float* Bs = smem_dyn + D * PAD;  // [D][PAD]

    const int tid  = threadIdx.x;
    const int row0 = blockIdx.y * BM;
    const int col0 = blockIdx.x * BN;

    // ---- load + transpose A tile (128 rows x 64 dims) into k-major smem ----
#pragma unroll
    for (int i = 0; i < 8; i++) {
        int id = i * 256 + tid;   // 0..2047
        int r  = id >> 4;         // 0..127
        int c4 = id & 15;         // 0..15 (float4 column)
        float4 v = *reinterpret_cast<const float4*>(
            A + (size_t)(row0 + r) * D + c4 * 4);
        As[(c4 * 4 + 0) * PAD + r] = v.x;
        As[(c4 * 4 + 1) * PAD + r] = v.y;
        As[(c4 * 4 + 2) * PAD + r] = v.z;
        As[(c4 * 4 + 3) * PAD + r] = v.w;
    }
    // ---- same for B tile ----
#pragma unroll
    for (int i = 0; i < 8; i++) {
        int id = i * 256 + tid;
        int r  = id >> 4;
        int c4 = id & 15;
        float4 v = *reinterpret_cast<const float4*>(
            B + (size_t)(col0 + r) * D + c4 * 4);
        Bs[(c4 * 4 + 0) * PAD + r] = v.x;
        Bs[(c4 * 4 + 1) * PAD + r] = v.y;
        Bs[(c4 * 4 + 2) * PAD + r] = v.z;
        Bs[(c4 * 4 + 3) * PAD + r] = v.w;
    }
    __syncthreads();

    const int tx = tid & 15;   // column group (8 cols)
    const int ty = tid >> 4;   // row group (8 rows)
    const float* ap = As + ty * 8;
    const float* bp = Bs + tx * 8;

    unsigned long long acc[8][4];
#pragma unroll
    for (int i = 0; i < 8; i++)
#pragma unroll
        for (int j = 0; j < 4; j++) acc[i][j] = 0ULL;  // (0.f, 0.f)

#pragma unroll 8
    for (int k = 0; k < D; k++) {
        // a: 8 rows' values at dim k (broadcast across tx within a warp)
        float4 a0 = *reinterpret_cast<const float4*>(ap + k * PAD);
        float4 a1 = *reinterpret_cast<const float4*>(ap + k * PAD + 4);
        // b: 8 cols' values at dim k, already pair-packed in memory
        ulonglong2 b0 = *reinterpret_cast<const ulonglong2*>(bp + k * PAD);
        ulonglong2 b1 = *reinterpret_cast<const ulonglong2*>(bp + k * PAD + 4);

        unsigned long long bb[4] = {b0.x, b0.y, b1.x, b1.y};
        unsigned long long ad[8];
        ad[0] = pack2(a0.x, a0.x);
        ad[1] = pack2(a0.y, a0.y);
        ad[2] = pack2(a0.z, a0.z);
        ad[3] = pack2(a0.w, a0.w);
        ad[4] = pack2(a1.x, a1.x);
        ad[5] = pack2(a1.y, a1.y);
        ad[6] = pack2(a1.z, a1.z);
        ad[7] = pack2(a1.w, a1.w);

#pragma unroll
        for (int i = 0; i < 8; i++)
#pragma unroll
            for (int j = 0; j < 4; j++)
                acc[i][j] = fma2(ad[i], bb[j], acc[i][j]);
    }

    // ---- epilogue: exp(min(xs + ys + 2*gamma*dot, 0)) ----
    float xs[8], ys8[8];
#pragma unroll
    for (int i = 0; i < 8; i++) xs[i] = g_xs[row0 + ty * 8 + i];
#pragma unroll
    for (int j = 0; j < 8; j++) ys8[j] = g_ys[col0 + tx * 8 + j];

#pragma unroll
    for (int i = 0; i < 8; i++) {
        float o[8];
#pragma unroll
        for (int j = 0; j < 4; j++) {
            float2 d = unpack2(acc[i][j]);
            float t0 = fminf(xs[i] + ys8[2 * j]     + 0.03125f * d.x, 0.f);
            float t1 = fminf(xs[i] + ys8[2 * j + 1] + 0.03125f * d.y, 0.f);
            o[2 * j]     = __expf(t0);
            o[2 * j + 1] = __expf(t1);
        }
        float* orow = out + (size_t)(row0 + ty * 8 + i) * N + col0 + tx * 8;
        *reinterpret_cast<float4*>(orow)     = make_float4(o[0], o[1], o[2], o[3]);
        *reinterpret_cast<float4*>(orow + 4) = make_float4(o[4], o[5], o[6], o[7]);
    }
}

// ---------------------------------------------------------------------------
extern "C" void kernel_launch(void* const* d_in, const int* in_sizes, int n_in,
                              void* d_out, int out_size) {
    const float* A = (const float*)d_in[0];  // data        [M, 64]
    const float* B = (const float*)d_in[1];  // support_vec [N, 64]
    float* out     = (float*)d_out;          // [M, N]

    const int M = in_sizes[0] / D;           // 8192
    const int N = in_sizes[1] / D;           // 8192

    // norms (warp per row)
    norm_kernel<<<(M + 7) / 8, 256>>>(A, M, 0);
    norm_kernel<<<(N + 7) / 8, 256>>>(B, N, 1);

    // main GEMM + exp epilogue
    const int smem_bytes = 2 * D * PAD * sizeof(float);  // 67584
    static_assert(2 * D * PAD * sizeof(float) == 67584, "smem size");
    cudaFuncSetAttribute(rbf_kernel,
                         cudaFuncAttributeMaxDynamicSharedMemorySize,
                         smem_bytes);
    dim3 grid(N / BN, M / BM);
    rbf_kernel<<<grid, 256, smem_bytes>>>(A, B, out, M, N);
}

// round 3
// speedup vs baseline: 2.1549x; 2.1549x over previous
#include <cuda_runtime.h>
#include <cuda_bf16.h>
#include <cstdint>

#define D      64
#define NROWS  8192
#define BM     128
#define BN     128
#define KS     128      // smem K extent: [hi(0..63) | lo(64..127)]
#define LDT    136      // smem row stride (bf16 elems): 272B, bank offset 4/row
#define GAMMA  0.015625f
#define TWOG   0.03125f

// ---------------- device scratch (no allocation allowed) ----------------
__device__ float g_xs[NROWS];
__device__ float g_ys[NROWS];
__device__ __nv_bfloat16 g_A2[NROWS * KS];   // [row][ hi(64) | lo(64) ]
__device__ __nv_bfloat16 g_B2[NROWS * KS];

// ---------------- prep: bf16 hi/lo split + (-gamma * ||row||^2) ----------------
// one warp per row; which: 0 -> A/xs, 1 -> B/ys
__global__ void __launch_bounds__(256)
prep_kernel(const float* __restrict__ X, int rows, int which) {
    int w    = blockIdx.x * 8 + (threadIdx.x >> 5);
    int lane = threadIdx.x & 31;
    if (w >= rows) return;
    const float* r = X + (size_t)w * D;
    float f0 = r[lane];
    float f1 = r[lane + 32];

    __nv_bfloat16* dst = which ? g_B2 : g_A2;
    __nv_bfloat16 h0 = __float2bfloat16_rn(f0);
    __nv_bfloat16 h1 = __float2bfloat16_rn(f1);
    size_t base = (size_t)w * KS;
    dst[base + lane]           = h0;                                     // hi
    dst[base + lane + 32]      = h1;
    dst[base + 64 + lane]      = __float2bfloat16_rn(f0 - __bfloat162float(h0)); // lo
    dst[base + 64 + lane + 32] = __float2bfloat16_rn(f1 - __bfloat162float(h1));

    float s = f0 * f0 + f1 * f1;
#pragma unroll
    for (int o = 16; o; o >>= 1) s += __shfl_xor_sync(0xffffffffu, s, o);
    if (lane == 0) (which ? g_ys : g_xs)[w] = -GAMMA * s;
}

// ---------------- mma.sync bf16 helper ----------------
__device__ __forceinline__ void mma16816(float* d, const uint32_t* a,
                                         const uint32_t* b) {
    asm volatile(
        "mma.sync.aligned.m16n8k16.row.col.f32.bf16.bf16.f32 "
        "{%0,%1,%2,%3}, {%4,%5,%6,%7}, {%8,%9}, {%0,%1,%2,%3};"
        : "+f"(d[0]), "+f"(d[1]), "+f"(d[2]), "+f"(d[3])
        : "r"(a[0]), "r"(a[1]), "r"(a[2]), "r"(a[3]), "r"(b[0]), "r"(b[1]));
}
__device__ __forceinline__ uint32_t lds32(const __nv_bfloat16* p) {
    return *reinterpret_cast<const uint32_t*>(p);
}

// ---------------- main: 128x128 tile, 8 warps, split-bf16 HMMA ----------------
extern __shared__ __nv_bfloat16 smem[];

__global__ void __launch_bounds__(256, 2)
rbf_mma_kernel(float* __restrict__ out, int N) {
    __nv_bfloat16* As = smem;                 // [128][LDT]
    __nv_bfloat16* Bs = smem + BM * LDT;      // [128][LDT]

    const int tid  = threadIdx.x;
    const int lane = tid & 31;
    const int wid  = tid >> 5;
    const int gID  = lane >> 2;   // 0..7
    const int tig  = lane & 3;    // 0..3
    const int wm   = wid >> 2;    // 0..1 : 64-row slab
    const int wn   = wid & 3;     // 0..3 : 32-col slab
    const int row0 = blockIdx.y * BM;
    const int col0 = blockIdx.x * BN;

    // ---- load tiles (128 rows x 128 bf16 each) into padded smem ----
    {
        const uint4* ga = reinterpret_cast<const uint4*>(g_A2 + (size_t)row0 * KS);
        const uint4* gb = reinterpret_cast<const uint4*>(g_B2 + (size_t)col0 * KS);
#pragma unroll
        for (int t = 0; t < 8; t++) {
            int id = t * 256 + tid;     // 0..2047
            int r  = id >> 4;           // 0..127
            int q  = id & 15;           // 16B chunk
            *reinterpret_cast<uint4*>(As + r * LDT + q * 8) = ga[r * 16 + q];
            *reinterpret_cast<uint4*>(Bs + r * LDT + q * 8) = gb[r * 16 + q];
        }
    }
    __syncthreads();

    // ---- 3 split terms: hiA*hiB + hiA*loB + loA*hiB ----
    float acc[4][4][4];
#pragma unroll
    for (int mt = 0; mt < 4; mt++)
#pragma unroll
        for (int nt = 0; nt < 4; nt++)
#pragma unroll
            for (int i = 0; i < 4; i++) acc[mt][nt][i] = 0.f;

    const __nv_bfloat16* ab = As + (wm * 64 + gID) * LDT + 2 * tig;
    const __nv_bfloat16* bb = Bs + (wn * 32 + gID) * LDT + 2 * tig;

    // pass group 1: A-hi frags, used against B-hi and B-lo
#pragma unroll
    for (int ks = 0; ks < 4; ks++) {
        const int k0 = ks * 16;
        uint32_t a[4][4];
#pragma unroll
        for (int mt = 0; mt < 4; mt++) {
            const __nv_bfloat16* p = ab + mt * 16 * LDT + k0;
            a[mt][0] = lds32(p);
            a[mt][1] = lds32(p + 8 * LDT);
            a[mt][2] = lds32(p + 8);
            a[mt][3] = lds32(p + 8 * LDT + 8);
        }
#pragma unroll
        for (int nt = 0; nt < 4; nt++) {            // B-hi
            const __nv_bfloat16* p = bb + nt * 8 * LDT + k0;
            uint32_t b[2] = {lds32(p), lds32(p + 8)};
#pragma unroll
            for (int mt = 0; mt < 4; mt++) mma16816(acc[mt][nt], a[mt], b);
        }
#pragma unroll
        for (int nt = 0; nt < 4; nt++) {            // B-lo
            const __nv_bfloat16* p = bb + nt * 8 * LDT + k0 + 64;
            uint32_t b[2] = {lds32(p), lds32(p + 8)};
#pragma unroll
            for (int mt = 0; mt < 4; mt++) mma16816(acc[mt][nt], a[mt], b);
        }
    }
    // pass group 2: A-lo x B-hi
#pragma unroll
    for (int ks = 0; ks < 4; ks++) {
        const int k0 = ks * 16;
        uint32_t a[4][4];
#pragma unroll
        for (int mt = 0; mt < 4; mt++) {
            const __nv_bfloat16* p = ab + mt * 16 * LDT + k0 + 64;
            a[mt][0] = lds32(p);
            a[mt][1] = lds32(p + 8 * LDT);
            a[mt][2] = lds32(p + 8);
            a[mt][3] = lds32(p + 8 * LDT + 8);
        }
#pragma unroll
        for (int nt = 0; nt < 4; nt++) {
            const __nv_bfloat16* p = bb + nt * 8 * LDT + k0;
            uint32_t b[2] = {lds32(p), lds32(p + 8)};
#pragma unroll
            for (int mt = 0; mt < 4; mt++) mma16816(acc[mt][nt], a[mt], b);
        }
    }

    // ---- epilogue: exp(min(xs + ys + 2*gamma*dot, 0)), coalesced float2 stores ----
    float xs0[4], xs1[4];
#pragma unroll
    for (int mt = 0; mt < 4; mt++) {
        int r = row0 + wm * 64 + mt * 16 + gID;
        xs0[mt] = g_xs[r];
        xs1[mt] = g_xs[r + 8];
    }
    float2 ysv[4];
#pragma unroll
    for (int nt = 0; nt < 4; nt++)
        ysv[nt] = *reinterpret_cast<const float2*>(
            &g_ys[col0 + wn * 32 + nt * 8 + 2 * tig]);

#pragma unroll
    for (int mt = 0; mt < 4; mt++) {
        int r = row0 + wm * 64 + mt * 16 + gID;
#pragma unroll
        for (int nt = 0; nt < 4; nt++) {
            int c = col0 + wn * 32 + nt * 8 + 2 * tig;
            float2 v0, v1;
            v0.x = __expf(fminf(xs0[mt] + ysv[nt].x + TWOG * acc[mt][nt][0], 0.f));
            v0.y = __expf(fminf(xs0[mt] + ysv[nt].y + TWOG * acc[mt][nt][1], 0.f));
            v1.x = __expf(fminf(xs1[mt] + ysv[nt].x + TWOG * acc[mt][nt][2], 0.f));
            v1.y = __expf(fminf(xs1[mt] + ysv[nt].y + TWOG * acc[mt][nt][3], 0.f));
            *reinterpret_cast<float2*>(out + (size_t)r * N + c)       = v0;
            *reinterpret_cast<float2*>(out + (size_t)(r + 8) * N + c) = v1;
        }
    }
}

// ---------------------------------------------------------------------------
extern "C" void kernel_launch(void* const* d_in, const int* in_sizes, int n_in,
                              void* d_out, int out_size) {
    const float* A = (const float*)d_in[0];  // data        [M, 64]
    const float* B = (const float*)d_in[1];  // support_vec [N, 64]
    float* out     = (float*)d_out;          // [M, N]

    const int M = in_sizes[0] / D;           // 8192
    const int N = in_sizes[1] / D;           // 8192

    prep_kernel<<<(M + 7) / 8, 256>>>(A, M, 0);
    prep_kernel<<<(N + 7) / 8, 256>>>(B, N, 1);

    const int smem_bytes = 2 * BM * LDT * sizeof(__nv_bfloat16);  // 69632
    cudaFuncSetAttribute(rbf_mma_kernel,
                         cudaFuncAttributeMaxDynamicSharedMemorySize, smem_bytes);
    dim3 grid(N / BN, M / BM);
    rbf_mma_kernel<<<grid, 256, smem_bytes>>>(out, N);
}